// round 5
// baseline (speedup 1.0000x reference)
#include <cuda_runtime.h>
#include <math.h>

// FlexibleLogisticModel: f = sigmoid( sum_f w[f] * alpha[ord(f)] * monomial_f(x) ),
// all multiset monomials deg 0..4 in D=64 vars, lex (CWR) order. Never reads E.
//
// Coalesced reformulation: TT[p] = x_{i3} x_{i4} over pairs i3<=i4 (lex, 2080
// entries, smem). Then
//   deg-4 = sum_{i1<=i2} x_i1 x_i2 * dot(w4_block(i1,i2), TT_tail(i2))
//   deg-3 = sum_{i1}     x_i1      * dot(w3_block(i1),    TT_tail(i1))
//   deg-2 =                          dot(w2,              TT)
// Every block is contiguous in w; warps process items cooperatively with
// lane-consecutive addresses -> 1 cache line per LDG (vs 32 before).
// Single fused kernel: last block applies sigmoid + resets accumulators.

#define D 64
#define NPAIR 2080          // C(65,2)
#define NITEMS 2146         // 2080 deg4-pairs + 64 deg3 + 1 deg2 + 1 deg01
#define TPB 256
#define NBLK 148            // one CTA per SM, single wave
#define NW (NBLK * (TPB / 32))   // 1184 warps

__device__ double   g_acc   = 0.0;
__device__ unsigned g_count = 0;

__device__ __forceinline__ int C2i(int n) { return (n >= 2) ? (n * (n - 1)) / 2 : 0; }
__device__ __forceinline__ int C3i(int n) { return (n >= 3) ? (n * (n - 1) * (n - 2)) / 6 : 0; }
__device__ __forceinline__ int C4i(int n) { return (n >= 4) ? (n * (n - 1) * (n - 2) * (n - 3)) / 24 : 0; }

// smallest n >= 2 with C2(n) >= v, v in [1, 2080]
__device__ __forceinline__ int inv_C2(int v) {
    int n = (int)(0.5f * (1.0f + sqrtf(8.0f * (float)v + 1.0f)));
    n = (n > 2) ? n - 1 : 2;
    while (C2i(n) < v) n++;
    return n;
}

__global__ void __launch_bounds__(TPB)
poly_fused_kernel(const float* __restrict__ x,
                  const float* __restrict__ w,
                  const float* __restrict__ alphas,
                  float* __restrict__ out)
{
    __shared__ float  xs[D];
    __shared__ float  al[5];
    __shared__ float  TT[NPAIR];
    __shared__ double warp_sums[TPB / 32];

    const int tid  = threadIdx.x;
    const int lane = tid & 31;
    if (tid < D) xs[tid] = x[tid];
    if (tid < 5) al[tid] = alphas[tid];
    __syncthreads();

    // Build TT: pair p=(i3,i4) lex -> xs[i3]*xs[i4]
    for (int e = tid; e < NPAIR; e += TPB) {
        const int rem = NPAIR - e;
        const int n = inv_C2(rem);         // n = 65 - i3
        const int i3 = 65 - n;
        const int i4 = i3 + (C2i(n) - rem);
        TT[e] = xs[i3] * xs[i4];
    }
    __syncthreads();

    const int gw = blockIdx.x * (TPB / 32) + (tid >> 5);
    double local = 0.0;

    for (int t = gw; t < NITEMS; t += NW) {
        const float* wp; const float* tp;
        int len; float scale;

        if (t < NPAIR) {
            // deg-4 item: pair (i1,i2), contiguous w4 block, TT tail
            const int rem = NPAIR - t;
            const int n = inv_C2(rem);     // n = 65 - i1
            const int i1 = 65 - n;
            const int i2 = i1 + (C2i(n) - rem);
            const int off = 47905
                          + (766480 - C4i(67 - i1))
                          + (C3i(66 - i1) - C3i(66 - i2));
            len   = C2i(65 - i2);
            wp    = w + off;
            tp    = TT + (NPAIR - len);
            scale = al[4] * xs[i1] * xs[i2];
        } else if (t < NPAIR + D) {
            // deg-3 item: leading i1
            const int i1 = t - NPAIR;
            const int off = 2145 + (45760 - C3i(66 - i1));
            len   = C2i(65 - i1);
            wp    = w + off;
            tp    = TT + (NPAIR - len);
            scale = al[3] * xs[i1];
        } else if (t == NPAIR + D) {
            // deg-2: dot(w2, TT) over all 2080 pairs
            len   = NPAIR;
            wp    = w + 65;
            tp    = TT;
            scale = al[2];
        } else {
            // deg-0 and deg-1 (64 + 1 terms), warp-cooperative
            float s = al[1] * (w[1 + lane] * xs[lane] + w[33 + lane] * xs[32 + lane]);
            if (lane == 0) s += w[0] * al[0];
            local += (double)s;
            continue;
        }

        // warp-cooperative coalesced dot: lane l covers l, l+32, ...
        float s0 = 0.f, s1 = 0.f, s2 = 0.f, s3 = 0.f;
        int k = lane;
        for (; k + 96 < len; k += 128) {
            const float a0 = wp[k];      const float a1 = wp[k + 32];
            const float a2 = wp[k + 64]; const float a3 = wp[k + 96];
            s0 += a0 * tp[k];      s1 += a1 * tp[k + 32];
            s2 += a2 * tp[k + 64]; s3 += a3 * tp[k + 96];
        }
        for (; k < len; k += 32) s0 += wp[k] * tp[k];
        // each lane's partial scaled identically; sum over lanes = scale * dot
        local += (double)(scale * ((s0 + s1) + (s2 + s3)));
    }

    // ---- warp + block reduction (double) ----
    #pragma unroll
    for (int o = 16; o > 0; o >>= 1)
        local += __shfl_down_sync(0xffffffffu, local, o);
    if (lane == 0) warp_sums[tid >> 5] = local;
    __syncthreads();

    if (tid == 0) {
        double bs = 0.0;
        #pragma unroll
        for (int i = 0; i < TPB / 32; i++) bs += warp_sums[i];
        atomicAdd(&g_acc, bs);
        __threadfence();
        const unsigned done = atomicAdd(&g_count, 1u);
        if (done == NBLK - 1) {
            const double a = atomicAdd(&g_acc, 0.0);  // all contributions visible
            out[0] = (float)(1.0 / (1.0 + exp(-a)));
            g_acc = 0.0;     // reset for next graph replay
            g_count = 0u;
        }
    }
}

extern "C" void kernel_launch(void* const* d_in, const int* in_sizes, int n_in,
                              void* d_out, int out_size)
{
    const float* x      = (const float*)d_in[0];
    const float* w      = (const float*)d_in[1];
    const float* alphas = (const float*)d_in[2];
    // d_in[3] = E (constant, NOT read), d_in[4] = ord_ids (NOT read)
    float* out = (float*)d_out;

    poly_fused_kernel<<<NBLK, TPB>>>(x, w, alphas, out);
}